// round 15
// baseline (speedup 1.0000x reference)
#include <cuda_runtime.h>
#include <cuda_bf16.h>
#include <cstdint>

// Sim2: temporal cost-volume + softmax + 1x1convs on a 3-level pyramid.
//   k_simcvt   : blocks 0-127 = cost volume partials (f32x2, past-in-regs);
//                blocks 128+  = fp32 -> split-bf16 planes of X and W (overlapped)
//   k_reduceT  : 16-chunk fold + transpose -> g_Lt[bt][px][81]
//   k_softmax1 : warp-per-(b,t,px) softmax(81) + conv1 + BN + SiLU
//   k_conv2t   : unified 3-level C->C tensor-core GEMM, double-buffered
//                cp.async staging from pre-split planes; fp32 pr/BN/SiLU epilogue

#define B_    4
#define C2    512
#define HW2   400
#define NS_   81
#define NCH   16
#define WROWS 18
#define CROW  29

__device__ float g_Lpart[NCH * 12 * NS_ * HW2];
__device__ float g_Lt[12 * HW2 * NS_];          // [bt][px][s]
__device__ float g_simf[B_ * 4 * HW2];

// X planes: lvl0 @0 (3276800), lvl1 @3276800 (1638400), lvl2 @4915200 (819200)
__device__ __align__(16) __nv_bfloat16 g_xh[5734400];
__device__ __align__(16) __nv_bfloat16 g_xl[5734400];
// W planes [o][k], k<C: lvl0 @0 (16384), lvl1 @16384 (65536), lvl2 @81920 (262144)
__device__ __align__(16) __nv_bfloat16 g_wh[344064];
__device__ __align__(16) __nv_bfloat16 g_wl[344064];

__device__ __forceinline__ void pack8(const float* v, uint4& hi, uint4& lo) {
    uint32_t h[4], l[4];
#pragma unroll
    for (int j = 0; j < 4; j++) {
        __nv_bfloat162 hh = __floats2bfloat162_rn(v[2*j], v[2*j+1]);
        float2 hf = __bfloat1622float2(hh);
        __nv_bfloat162 ll = __floats2bfloat162_rn(v[2*j] - hf.x, v[2*j+1] - hf.y);
        h[j] = *reinterpret_cast<uint32_t*>(&hh);
        l[j] = *reinterpret_cast<uint32_t*>(&ll);
    }
    hi = make_uint4(h[0], h[1], h[2], h[3]);
    lo = make_uint4(l[0], l[1], l[2], l[3]);
}

__device__ __forceinline__ unsigned long long addx2(unsigned long long a,
                                                    unsigned long long b) {
    unsigned long long r;
    asm("add.rn.f32x2 %0, %1, %2;" : "=l"(r) : "l"(a), "l"(b));
    return r;
}
__device__ __forceinline__ unsigned long long packx2(float lo, float hi) {
    unsigned long long r;
    asm("mov.b64 %0, {%1, %2};" : "=l"(r) : "f"(lo), "f"(hi));
    return r;
}

__device__ __forceinline__ void cpasync16(uint32_t saddr, const void* g) {
    asm volatile("cp.async.cg.shared.global [%0], [%1], 16;\n"
        :: "r"(saddr), "l"(g));
}
__device__ __forceinline__ void cpasync16z(uint32_t saddr, const void* g, int sz) {
    asm volatile("cp.async.cg.shared.global [%0], [%1], 16, %2;\n"
        :: "r"(saddr), "l"(g), "r"(sz));
}

// ---------------------------------------------------------------------------
// Fused kernel: sim (blocks 0..127) + X/W plane conversion (blocks 128..975).
// 224 threads. Conversion: 848 blocks x 4 items/thread (759808 items total).
// ---------------------------------------------------------------------------
__global__ __launch_bounds__(224) void k_simcvt(
    const float* __restrict__ f0, const float* __restrict__ f1,
    const float* __restrict__ f2,
    const float* __restrict__ w0, const float* __restrict__ w1,
    const float* __restrict__ w2)
{
    extern __shared__ unsigned long long curS2[];   // sim blocks only

    int bidx = blockIdx.x;
    int tid  = threadIdx.x;

    if (bidx >= 128) {
        // ---- conversion blocks ----
        int base = (bidx - 128) * 896;
#pragma unroll
        for (int j = 0; j < 4; j++) {
            int idx = base + j * 224 + tid;
            if (idx >= 759808) continue;
            if (idx < 716800) {   // activations
                const float* src; size_t dstOff; int CHW, e;
                if (idx < 409600)      { src = f0; dstOff = 0;       CHW = 128 * 6400; e = idx * 8; }
                else if (idx < 614400) { src = f1; dstOff = 3276800; CHW = 256 * 1600; e = (idx - 409600) * 8; }
                else                   { src = f2; dstOff = 4915200; CHW = 512 * 400;  e = (idx - 614400) * 8; }
                int b = e / CHW;
                int r = e - b * CHW;
                const float* s = src + (size_t)(b * 4 + 3) * CHW + r;
                float v[8];
                *(float4*)v       = *(const float4*)s;
                *(float4*)(v + 4) = *(const float4*)(s + 4);
                uint4 hi, lo; pack8(v, hi, lo);
                *(uint4*)(g_xh + dstOff + (size_t)b * CHW + r) = hi;
                *(uint4*)(g_xl + dstOff + (size_t)b * CHW + r) = lo;
            } else {              // weights
                int wi = idx - 716800;
                const float* w; size_t dstOff; int C, e;
                if (wi < 2048)       { w = w0; dstOff = 0;     C = 128; e = wi * 8; }
                else if (wi < 10240) { w = w1; dstOff = 16384; C = 256; e = (wi - 2048) * 8; }
                else                 { w = w2; dstOff = 81920; C = 512; e = (wi - 10240) * 8; }
                int o = e / C, k = e - o * C;
                const float* s = w + (size_t)o * (C + 4) + k;
                float v[8];
#pragma unroll
                for (int q = 0; q < 8; q++) v[q] = s[q];
                uint4 hi, lo; pack8(v, hi, lo);
                *(uint4*)(g_wh + dstOff + e) = hi;
                *(uint4*)(g_wl + dstOff + e) = lo;
            }
        }
        return;
    }

    // ---- sim blocks ----
    int cc = bidx & 15;
    int b  = (bidx >> 4) & 3;
    int h  = bidx >> 6;
    int r0 = h * 10;

    const float* curG = f2 + ((size_t)(b * 4 + 3) * C2 + cc * 32) * HW2;

    for (int i = tid; i < 16 * WROWS * 28; i += 224) {
        int c2  = i / (WROWS * 28);
        int rem = i - c2 * (WROWS * 28);
        int wr  = rem / 28, wc = rem - wr * 28;
        int gy  = r0 + wr - 4, gx = wc - 4;
        float lo = 0.f, hi = 0.f;
        if ((unsigned)gy < 20u && (unsigned)gx < 20u) {
            int g = gy * 20 + gx;
            lo = curG[(2 * c2) * HW2 + g];
            hi = curG[(2 * c2 + 1) * HW2 + g];
        }
        curS2[c2 * (WROWS * CROW) + wr * CROW + wc] = packx2(lo, hi);
    }
    __syncthreads();

    if (tid < 200) {
        unsigned long long np[3][16];
#pragma unroll
        for (int t = 0; t < 3; t++) {
            const float* pb = f2 + ((size_t)(b * 4 + t) * C2 + cc * 32) * HW2
                            + r0 * 20 + tid;
#pragma unroll
            for (int c2 = 0; c2 < 16; c2++)
                np[t][c2] = packx2(-pb[(2 * c2) * HW2], -pb[(2 * c2 + 1) * HW2]);
        }

        int lr  = tid / 20;
        int col = tid - lr * 20;
        size_t obase = (((size_t)cc * 12 + b * 3) * NS_) * HW2 + h * 200 + tid;
        const unsigned long long SGN = 0x8000000080000000ULL;

        for (int s = 0; s < NS_; s++) {
            int dy = s / 9, dx = s - dy * 9;
            const unsigned long long* cp =
                curS2 + (lr + dy) * CROW + col + dx;
            unsigned long long a0 = 0ULL, a1 = 0ULL, a2 = 0ULL;
#pragma unroll
            for (int c2 = 0; c2 < 16; c2++) {
                unsigned long long cv = cp[c2 * (WROWS * CROW)];
                unsigned long long d0 = addx2(cv, np[0][c2]);
                unsigned long long d1 = addx2(cv, np[1][c2]);
                unsigned long long d2 = addx2(cv, np[2][c2]);
                a0 = addx2(a0, d0 | SGN);
                a1 = addx2(a1, d1 | SGN);
                a2 = addx2(a2, d2 | SGN);
            }
            float r0f = __uint_as_float((unsigned)a0) + __uint_as_float((unsigned)(a0 >> 32));
            float r1f = __uint_as_float((unsigned)a1) + __uint_as_float((unsigned)(a1 >> 32));
            float r2f = __uint_as_float((unsigned)a2) + __uint_as_float((unsigned)(a2 >> 32));
            size_t o = obase + (size_t)s * HW2;
            g_Lpart[o]                         = r0f;
            g_Lpart[o + (size_t)NS_ * HW2]     = r1f;
            g_Lpart[o + (size_t)2 * NS_ * HW2] = r2f;
        }
    }
}

// ---------------------------------------------------------------------------
// Kernel: 16-chunk fold + transpose. grid = (25, 12), 256 threads.
// ---------------------------------------------------------------------------
__global__ __launch_bounds__(256) void k_reduceT()
{
    __shared__ float ts[NS_][17];

    int bt  = blockIdx.y;
    int px0 = blockIdx.x * 16;
    int tid = threadIdx.x;

    int sr = tid >> 4;
    int pc = tid & 15;

    const float* base = g_Lpart + (size_t)bt * NS_ * HW2 + px0 + pc;
    for (int s = sr; s < NS_; s += 16) {
        const float* src = base + (size_t)s * HW2;
        float a = 0.f;
#pragma unroll
        for (int cc = 0; cc < NCH; cc++)
            a += src[(size_t)cc * (12 * NS_ * HW2)];
        ts[s][pc] = a;
    }
    __syncthreads();

    int pxl = tid >> 4, sc = tid & 15;
    float* dst = g_Lt + ((size_t)bt * HW2 + px0 + pxl) * NS_;
    for (int s = sc; s < NS_; s += 16)
        dst[s] = ts[s][pxl];
}

// ---------------------------------------------------------------------------
// Kernel: warp-per-(b,t,px) softmax(81) + conv1(243->4) + BN + SiLU.
// grid = (100, B), 384 threads = 12 warps = 4 px x 3 t. Coalesced s-loads.
// ---------------------------------------------------------------------------
__global__ __launch_bounds__(384) void k_softmax1(
    const float* __restrict__ w1,
    const float* __restrict__ g1, const float* __restrict__ b1,
    const float* __restrict__ m1, const float* __restrict__ v1)
{
    __shared__ float w1s[992];
    __shared__ float opart[3][4][4];

    int b    = blockIdx.y;
    int tid  = threadIdx.x;
    int w    = tid >> 5;
    int lane = tid & 31;
    int pxl  = w / 3;
    int t    = w - pxl * 3;

    for (int i = tid; i < 992; i += 384) w1s[i] = (i < 972) ? w1[i] : 0.f;
    __syncthreads();

    int px = blockIdx.x * 4 + pxl;
    const float* Lb = g_Lt + ((size_t)(b * 3 + t) * HW2 + px) * NS_;

    bool has2 = lane < 17;
    float e0 = Lb[lane];
    float e1 = Lb[lane + 32];
    float e2 = has2 ? Lb[lane + 64] : -1e30f;

    float mx = fmaxf(fmaxf(e0, e1), e2);
#pragma unroll
    for (int off = 16; off; off >>= 1)
        mx = fmaxf(mx, __shfl_xor_sync(0xffffffffu, mx, off));

    float x0 = __expf(e0 - mx);
    float x1 = __expf(e1 - mx);
    float x2 = has2 ? __expf(e2 - mx) : 0.f;

    const float* wt = w1s + t * 81;
    float z  = x0 + x1 + x2;
    float u0 = wt[lane] * x0       + wt[lane + 32] * x1       + wt[lane + 64] * x2;
    float u1 = wt[243 + lane] * x0 + wt[243 + lane + 32] * x1 + wt[243 + lane + 64] * x2;
    float u2 = wt[486 + lane] * x0 + wt[486 + lane + 32] * x1 + wt[486 + lane + 64] * x2;
    float u3 = wt[729 + lane] * x0 + wt[729 + lane + 32] * x1 + wt[729 + lane + 64] * x2;

#pragma unroll
    for (int off = 16; off; off >>= 1) {
        z  += __shfl_xor_sync(0xffffffffu, z,  off);
        u0 += __shfl_xor_sync(0xffffffffu, u0, off);
        u1 += __shfl_xor_sync(0xffffffffu, u1, off);
        u2 += __shfl_xor_sync(0xffffffffu, u2, off);
        u3 += __shfl_xor_sync(0xffffffffu, u3, off);
    }

    if (lane == 0) {
        float rz = 1.f / z;
        opart[t][0][pxl] = u0 * rz;
        opart[t][1][pxl] = u1 * rz;
        opart[t][2][pxl] = u2 * rz;
        opart[t][3][pxl] = u3 * rz;
    }
    __syncthreads();

    if (tid < 16) {
        int pl = tid >> 2, oc = tid & 3;
        float o = opart[0][oc][pl] + opart[1][oc][pl] + opart[2][oc][pl];
        float sc = g1[oc] * rsqrtf(v1[oc] + 1e-3f);
        float yv = (o - m1[oc]) * sc + b1[oc];
        g_simf[((size_t)b * 4 + oc) * HW2 + blockIdx.x * 4 + pl]
            = yv / (1.f + __expf(-yv));
    }
}

// ---------------------------------------------------------------------------
// Kernel: unified tensor-core conv2. BM=64 x BN=128, 256 threads, occ 2.
// DOUBLE-BUFFERED cp.async staging from pre-split bf16 planes.
// smem: buf0 [WH|WL|XH|XL] @0..48K, buf1 @48K..96K, prS @96K, wprS @98K+2K
// ---------------------------------------------------------------------------
struct LvP {
    const __nv_bfloat16 *xh, *xl, *wh, *wl;
    const float* w;
    const float* gg; const float* bb; const float* mm; const float* vv;
    float* out;
    int C, HW, Wo, nt, mt, blk0;
};
struct AllP { LvP lv[3]; };   // lv[0]=level2(heavy), lv[1]=level1, lv[2]=level0

__device__ __forceinline__ void ldsm4(uint32_t* r, uint32_t a) {
    asm volatile("ldmatrix.sync.aligned.m8n8.x4.shared.b16 {%0,%1,%2,%3},[%4];\n"
        : "=r"(r[0]), "=r"(r[1]), "=r"(r[2]), "=r"(r[3]) : "r"(a));
}
__device__ __forceinline__ void ldsm4t(uint32_t* r, uint32_t a) {
    asm volatile("ldmatrix.sync.aligned.m8n8.x4.trans.shared.b16 {%0,%1,%2,%3},[%4];\n"
        : "=r"(r[0]), "=r"(r[1]), "=r"(r[2]), "=r"(r[3]) : "r"(a));
}
__device__ __forceinline__ void mma16816(float* d, const uint32_t* a,
                                         uint32_t b0, uint32_t b1) {
    asm volatile("mma.sync.aligned.m16n8k16.row.col.f32.bf16.bf16.f32 "
        "{%0,%1,%2,%3},{%4,%5,%6,%7},{%8,%9},{%0,%1,%2,%3};\n"
        : "+f"(d[0]), "+f"(d[1]), "+f"(d[2]), "+f"(d[3])
        : "r"(a[0]), "r"(a[1]), "r"(a[2]), "r"(a[3]), "r"(b0), "r"(b1));
}

__global__ __launch_bounds__(256, 2) void k_conv2t(AllP P)
{
    extern __shared__ char smc[];
    const int BUFSZ = 49152;
    const int OFF_WL = 8192, OFF_XH = 16384, OFF_XL = 32768;
    float* prS  = (float*)(smc + 98304);   // [4][128]
    float* wprS = (float*)(smc + 100352);  // [64][4]

    int bid = blockIdx.x;
    int li  = (bid >= P.lv[1].blk0) + (bid >= P.lv[2].blk0);
    LvP L = P.lv[li];

    int rb     = bid - L.blk0;
    int n_tile = rb % L.nt;
    int r2     = rb / L.nt;
    int m_tile = r2 % L.mt;
    int b      = r2 / L.mt;

    int ptile  = n_tile * 128;
    int K      = L.C + 4;
    int nchunk = L.C >> 6;

    int tid = threadIdx.x;
    int lane = tid & 31, wid = tid >> 5;
    int wm = wid >> 2, wn = wid & 3;

    uint32_t sb = (uint32_t)__cvta_generic_to_shared(smc);

    const __nv_bfloat16* xhb = L.xh + (size_t)b * L.C * L.HW;
    const __nv_bfloat16* xlb = L.xl + (size_t)b * L.C * L.HW;
    const __nv_bfloat16* whb = L.wh + (size_t)m_tile * 64 * L.C;
    const __nv_bfloat16* wlb = L.wl + (size_t)m_tile * 64 * L.C;

    // pr tile: bilinear from g_simf (identity when Wo == 20)
    for (int i = tid; i < 512; i += 256) {
        int j = i >> 7, n = i & 127;
        int px = ptile + n;
        float v = 0.f;
        if (px < L.HW) {
            const float* sp = g_simf + (size_t)(b * 4 + j) * HW2;
            if (L.Wo == 20) {
                v = sp[px];
            } else {
                int yo = px / L.Wo, xo = px - yo * L.Wo;
                float s19 = 19.f / (float)(L.Wo - 1);
                float cy = yo * s19, cx = xo * s19;
                int y0 = (int)cy, x0 = (int)cx;
                int y1 = min(y0 + 1, 19), x1 = min(x0 + 1, 19);
                float wy = cy - (float)y0, wx = cx - (float)x0;
                v = (1.f - wy) * ((1.f - wx) * sp[y0 * 20 + x0] + wx * sp[y0 * 20 + x1])
                  +         wy * ((1.f - wx) * sp[y1 * 20 + x0] + wx * sp[y1 * 20 + x1]);
            }
        }
        prS[i] = v;
    }
    {
        int o = tid >> 2, jj = tid & 3;
        wprS[tid] = L.w[(size_t)(m_tile * 64 + o) * K + L.C + jj];
    }

    float acc[2][4][4];
#pragma unroll
    for (int i = 0; i < 2; i++)
#pragma unroll
        for (int j = 0; j < 4; j++)
#pragma unroll
            for (int q = 0; q < 4; q++) acc[i][j][q] = 0.f;

    // -------- staging (cp.async only) --------
    auto stage = [&](int c) {
        uint32_t sbb = sb + (c & 1) * BUFSZ;
        int kbase = c * 64;
#pragma unroll
        for (int it = 0; it < 2; it++) {
            int item = tid + it * 256;
            int o = item >> 3, u = item & 7;
            size_t si = (size_t)o * L.C + kbase + u * 8;
            int off = o * 128 + ((u ^ (o & 7)) << 4);
            cpasync16(sbb + off, whb + si);
            cpasync16(sbb + OFF_WL + off, wlb + si);
        }
#pragma unroll
        for (int it = 0; it < 4; it++) {
            int item = tid + it * 256;
            int kl = item >> 4, u = item & 15;
            int px0 = ptile + u * 8;
            size_t si = (size_t)(kbase + kl) * L.HW + px0;
            int off = kl * 256 + ((u ^ (kl & 7)) << 4);
            int sz = (px0 < L.HW) ? 16 : 0;
            cpasync16z(sbb + OFF_XH + off, xhb + si, sz);
            cpasync16z(sbb + OFF_XL + off, xlb + si, sz);
        }
        asm volatile("cp.async.commit_group;\n");
    };

    stage(0);

    for (int c = 0; c < nchunk; c++) {
        if (c + 1 < nchunk) {
            stage(c + 1);
            asm volatile("cp.async.wait_group 1;\n" ::: "memory");
        } else {
            asm volatile("cp.async.wait_group 0;\n" ::: "memory");
        }
        __syncthreads();

        uint32_t sbb = sb + (c & 1) * BUFSZ;
#pragma unroll
        for (int ks = 0; ks < 4; ks++) {
            uint32_t ah[2][4], al[2][4];
#pragma unroll
            for (int mi = 0; mi < 2; mi++) {
                int rr = wm * 32 + mi * 16 + (lane & 15);
                int ku = ks * 2 + (lane >> 4);
                uint32_t a = sbb + rr * 128 + ((ku ^ (rr & 7)) << 4);
                ldsm4(ah[mi], a);
                ldsm4(al[mi], a + OFF_WL);
            }
            uint32_t bh[2][4], bl[2][4];
#pragma unroll
            for (int g = 0; g < 2; g++) {
                int kr = ks * 16 + (lane & 15);
                int n0 = wn * 32 + g * 16 + ((lane >> 4) * 8);
                uint32_t a = sbb + OFF_XH + kr * 256 + (((n0 >> 3) ^ (kr & 7)) << 4);
                ldsm4t(bh[g], a);
                ldsm4t(bl[g], a + (OFF_XL - OFF_XH));
            }
#pragma unroll
            for (int mi = 0; mi < 2; mi++)
#pragma unroll
                for (int g = 0; g < 2; g++)
#pragma unroll
                    for (int t = 0; t < 2; t++) {
                        int ni = g * 2 + t;
                        mma16816(acc[mi][ni], ah[mi], bh[g][2*t], bh[g][2*t + 1]);
                        mma16816(acc[mi][ni], ah[mi], bl[g][2*t], bl[g][2*t + 1]);
                        mma16816(acc[mi][ni], al[mi], bh[g][2*t], bh[g][2*t + 1]);
                    }
        }
        __syncthreads();
    }

    int ro = lane >> 2, co = (lane & 3) * 2;
#pragma unroll
    for (int mi = 0; mi < 2; mi++) {
#pragma unroll
        for (int half = 0; half < 2; half++) {
            int rloc = wm * 32 + mi * 16 + half * 8 + ro;
            int oo = m_tile * 64 + rloc;
            float w0 = wprS[rloc * 4 + 0], w1 = wprS[rloc * 4 + 1];
            float w2 = wprS[rloc * 4 + 2], w3 = wprS[rloc * 4 + 3];
            float sc = L.gg[oo] * rsqrtf(L.vv[oo] + 1e-3f);
            float sh = L.bb[oo] - L.mm[oo] * sc;
            float* ob = L.out + (size_t)(b * L.C + oo) * L.HW;
#pragma unroll
            for (int ni = 0; ni < 4; ni++) {
                int nloc = wn * 32 + ni * 8 + co;
                int px = ptile + nloc;
                if (px < L.HW) {
                    float p0 = acc[mi][ni][half * 2 + 0]
                             + w0 * prS[nloc]       + w1 * prS[128 + nloc]
                             + w2 * prS[256 + nloc] + w3 * prS[384 + nloc];
                    float p1 = acc[mi][ni][half * 2 + 1]
                             + w0 * prS[nloc + 1]       + w1 * prS[128 + nloc + 1]
                             + w2 * prS[256 + nloc + 1] + w3 * prS[384 + nloc + 1];
                    float y0 = p0 * sc + sh;
                    float y1 = p1 * sc + sh;
                    float2 r;
                    r.x = y0 / (1.f + __expf(-y0));
                    r.y = y1 / (1.f + __expf(-y1));
                    *(float2*)(ob + px) = r;
                }
            }
        }
    }
}

// ---------------------------------------------------------------------------
// Launch
// ---------------------------------------------------------------------------
extern "C" void kernel_launch(void* const* d_in, const int* in_sizes, int n_in,
                              void* d_out, int out_size)
{
    const float *f0 = nullptr, *f1 = nullptr, *f2 = nullptr, *w1 = nullptr;
    const float* bn1[4] = {nullptr, nullptr, nullptr, nullptr};
    const float* w2[3]  = {nullptr, nullptr, nullptr};
    const float* bn2[3][4];

    for (int i = 0; i < n_in; i++) {
        int sz = in_sizes[i];
        if (sz == 13107200)      f0 = (const float*)d_in[i];
        else if (sz == 6553600)  f1 = (const float*)d_in[i];
        else if (sz == 3276800)  f2 = (const float*)d_in[i];
        else if (sz == 972) {
            w1 = (const float*)d_in[i];
            for (int j = 0; j < 4; j++) bn1[j] = (const float*)d_in[i + 1 + j];
        } else if (sz == 16896) {
            w2[0] = (const float*)d_in[i];
            for (int j = 0; j < 4; j++) bn2[0][j] = (const float*)d_in[i + 1 + j];
        } else if (sz == 66560) {
            w2[1] = (const float*)d_in[i];
            for (int j = 0; j < 4; j++) bn2[1][j] = (const float*)d_in[i + 1 + j];
        } else if (sz == 264192) {
            w2[2] = (const float*)d_in[i];
            for (int j = 0; j < 4; j++) bn2[2][j] = (const float*)d_in[i + 1 + j];
        }
    }
    if (!f0 || !f1 || !f2 || !w1 || !w2[0] || !w2[1] || !w2[2]) return;

    int sim_smem = 16 * WROWS * CROW * 8;          // 66816 B
    cudaFuncSetAttribute(k_simcvt, cudaFuncAttributeMaxDynamicSharedMemorySize, sim_smem);
    cudaFuncSetAttribute(k_conv2t, cudaFuncAttributeMaxDynamicSharedMemorySize, 101376);

    void *xh, *xl, *wh, *wl;
    cudaGetSymbolAddress(&xh, g_xh);
    cudaGetSymbolAddress(&xl, g_xl);
    cudaGetSymbolAddress(&wh, g_wh);
    cudaGetSymbolAddress(&wl, g_wl);
    const __nv_bfloat16* XH = (const __nv_bfloat16*)xh;
    const __nv_bfloat16* XL = (const __nv_bfloat16*)xl;
    const __nv_bfloat16* WH = (const __nv_bfloat16*)wh;
    const __nv_bfloat16* WL = (const __nv_bfloat16*)wl;

    float* out0 = (float*)d_out;
    float* out1 = out0 + (size_t)B_ * 128 * 6400;
    float* out2 = out1 + (size_t)B_ * 256 * 1600;

    k_simcvt<<<976, 224, sim_smem>>>(f0, f1, f2, w2[0], w2[1], w2[2]);
    k_reduceT<<<dim3(25, 12), 256>>>();
    k_softmax1<<<dim3(100, B_), 384>>>(w1, bn1[0], bn1[1], bn1[2], bn1[3]);

    // heavy-first block order: level2 (8 chunks) -> level1 (4) -> level0 (2)
    AllP P;
    P.lv[0] = { XH + 4915200, XL + 4915200, WH + 81920, WL + 81920, w2[2],
                bn2[2][0], bn2[2][1], bn2[2][2], bn2[2][3],
                out2, 512, 400, 20, 4, 8, 0 };      // 128 blocks
    P.lv[1] = { XH + 3276800, XL + 3276800, WH + 16384, WL + 16384, w2[1],
                bn2[1][0], bn2[1][1], bn2[1][2], bn2[1][3],
                out1, 256, 1600, 40, 13, 4, 128 };  // 208 blocks
    P.lv[2] = { XH, XL, WH, WL, w2[0],
                bn2[0][0], bn2[0][1], bn2[0][2], bn2[0][3],
                out0, 128, 6400, 80, 50, 2, 336 };  // 400 blocks
    int total_blocks = 128 + 208 + 400;   // 736

    k_conv2t<<<total_blocks, 256, 101376>>>(P);
}

// round 17
// speedup vs baseline: 1.2340x; 1.2340x over previous
#include <cuda_runtime.h>
#include <cuda_bf16.h>
#include <cstdint>

// Sim2: temporal cost-volume + softmax + 1x1convs on a 3-level pyramid.
//   k_sim      : cost volume partials, f32x2 packed math, past-in-registers
//   k_rcvt     : blocks 0-299 = 16-chunk fold + transpose -> g_Lt;
//                blocks 300+  = fp32 -> split-bf16 planes of X and W
//                (small static smem -> cvt blocks run at full occupancy)
//   k_softmax1 : warp-per-(b,t,px) softmax(81) + conv1 + BN + SiLU
//   k_conv2t   : unified 3-level C->C tensor-core GEMM, occ3, pure cp.async
//                staging from pre-split planes; bilinear pr in-prologue

#define B_    4
#define C2    512
#define HW2   400
#define NS_   81
#define NCH   16
#define WROWS 18
#define CROW  29

__device__ float g_Lpart[NCH * 12 * NS_ * HW2];
__device__ float g_Lt[12 * HW2 * NS_];          // [bt][px][s]
__device__ float g_simf[B_ * 4 * HW2];

// X planes: lvl0 @0 (3276800), lvl1 @3276800 (1638400), lvl2 @4915200 (819200)
__device__ __align__(16) __nv_bfloat16 g_xh[5734400];
__device__ __align__(16) __nv_bfloat16 g_xl[5734400];
// W planes [o][k], k<C: lvl0 @0 (16384), lvl1 @16384 (65536), lvl2 @81920 (262144)
__device__ __align__(16) __nv_bfloat16 g_wh[344064];
__device__ __align__(16) __nv_bfloat16 g_wl[344064];

__device__ __forceinline__ void pack8(const float* v, uint4& hi, uint4& lo) {
    uint32_t h[4], l[4];
#pragma unroll
    for (int j = 0; j < 4; j++) {
        __nv_bfloat162 hh = __floats2bfloat162_rn(v[2*j], v[2*j+1]);
        float2 hf = __bfloat1622float2(hh);
        __nv_bfloat162 ll = __floats2bfloat162_rn(v[2*j] - hf.x, v[2*j+1] - hf.y);
        h[j] = *reinterpret_cast<uint32_t*>(&hh);
        l[j] = *reinterpret_cast<uint32_t*>(&ll);
    }
    hi = make_uint4(h[0], h[1], h[2], h[3]);
    lo = make_uint4(l[0], l[1], l[2], l[3]);
}

__device__ __forceinline__ unsigned long long addx2(unsigned long long a,
                                                    unsigned long long b) {
    unsigned long long r;
    asm("add.rn.f32x2 %0, %1, %2;" : "=l"(r) : "l"(a), "l"(b));
    return r;
}
__device__ __forceinline__ unsigned long long packx2(float lo, float hi) {
    unsigned long long r;
    asm("mov.b64 %0, {%1, %2};" : "=l"(r) : "f"(lo), "f"(hi));
    return r;
}

__device__ __forceinline__ void cpasync16(uint32_t saddr, const void* g) {
    asm volatile("cp.async.cg.shared.global [%0], [%1], 16;\n"
        :: "r"(saddr), "l"(g));
}
__device__ __forceinline__ void cpasync16z(uint32_t saddr, const void* g, int sz) {
    asm volatile("cp.async.cg.shared.global [%0], [%1], 16, %2;\n"
        :: "r"(saddr), "l"(g), "r"(sz));
}

// ---------------------------------------------------------------------------
// Kernel: cost volume partials, f32x2 packed. grid = (NCH, B, 2), 224 thr.
// ---------------------------------------------------------------------------
__global__ __launch_bounds__(224) void k_sim(const float* __restrict__ f2)
{
    extern __shared__ unsigned long long curS2[];   // [16][WROWS*CROW]

    int cc = blockIdx.x;
    int b  = blockIdx.y;
    int h  = blockIdx.z;

    int tid = threadIdx.x;
    int r0  = h * 10;

    const float* curG = f2 + ((size_t)(b * 4 + 3) * C2 + cc * 32) * HW2;

    for (int i = tid; i < 16 * WROWS * 28; i += 224) {
        int c2  = i / (WROWS * 28);
        int rem = i - c2 * (WROWS * 28);
        int wr  = rem / 28, wc = rem - wr * 28;
        int gy  = r0 + wr - 4, gx = wc - 4;
        float lo = 0.f, hi = 0.f;
        if ((unsigned)gy < 20u && (unsigned)gx < 20u) {
            int g = gy * 20 + gx;
            lo = curG[(2 * c2) * HW2 + g];
            hi = curG[(2 * c2 + 1) * HW2 + g];
        }
        curS2[c2 * (WROWS * CROW) + wr * CROW + wc] = packx2(lo, hi);
    }
    __syncthreads();

    if (tid < 200) {
        unsigned long long np[3][16];
#pragma unroll
        for (int t = 0; t < 3; t++) {
            const float* pb = f2 + ((size_t)(b * 4 + t) * C2 + cc * 32) * HW2
                            + r0 * 20 + tid;
#pragma unroll
            for (int c2 = 0; c2 < 16; c2++)
                np[t][c2] = packx2(-pb[(2 * c2) * HW2], -pb[(2 * c2 + 1) * HW2]);
        }

        int lr  = tid / 20;
        int col = tid - lr * 20;
        size_t obase = (((size_t)cc * 12 + b * 3) * NS_) * HW2 + h * 200 + tid;
        const unsigned long long SGN = 0x8000000080000000ULL;

        for (int s = 0; s < NS_; s++) {
            int dy = s / 9, dx = s - dy * 9;
            const unsigned long long* cp =
                curS2 + (lr + dy) * CROW + col + dx;
            unsigned long long a0 = 0ULL, a1 = 0ULL, a2 = 0ULL;
#pragma unroll
            for (int c2 = 0; c2 < 16; c2++) {
                unsigned long long cv = cp[c2 * (WROWS * CROW)];
                unsigned long long d0 = addx2(cv, np[0][c2]);
                unsigned long long d1 = addx2(cv, np[1][c2]);
                unsigned long long d2 = addx2(cv, np[2][c2]);
                a0 = addx2(a0, d0 | SGN);
                a1 = addx2(a1, d1 | SGN);
                a2 = addx2(a2, d2 | SGN);
            }
            float r0f = __uint_as_float((unsigned)a0) + __uint_as_float((unsigned)(a0 >> 32));
            float r1f = __uint_as_float((unsigned)a1) + __uint_as_float((unsigned)(a1 >> 32));
            float r2f = __uint_as_float((unsigned)a2) + __uint_as_float((unsigned)(a2 >> 32));
            size_t o = obase + (size_t)s * HW2;
            g_Lpart[o]                         = r0f;
            g_Lpart[o + (size_t)NS_ * HW2]     = r1f;
            g_Lpart[o + (size_t)2 * NS_ * HW2] = r2f;
        }
    }
}

// ---------------------------------------------------------------------------
// Fused kernel: reduce+transpose (blocks 0..299) + X/W conversion (300..1041).
// 256 threads, small static smem only.
// ---------------------------------------------------------------------------
__global__ __launch_bounds__(256) void k_rcvt(
    const float* __restrict__ f0, const float* __restrict__ f1,
    const float* __restrict__ f2,
    const float* __restrict__ w0, const float* __restrict__ w1,
    const float* __restrict__ w2)
{
    __shared__ float ts[NS_][17];

    int bid = blockIdx.x;
    int tid = threadIdx.x;

    if (bid >= 300) {
        // ---- conversion blocks: 742 x 1024 items ----
        int base = (bid - 300) * 1024;
#pragma unroll
        for (int j = 0; j < 4; j++) {
            int idx = base + j * 256 + tid;
            if (idx >= 759808) continue;
            if (idx < 716800) {   // activations
                const float* src; size_t dstOff; int CHW, e;
                if (idx < 409600)      { src = f0; dstOff = 0;       CHW = 128 * 6400; e = idx * 8; }
                else if (idx < 614400) { src = f1; dstOff = 3276800; CHW = 256 * 1600; e = (idx - 409600) * 8; }
                else                   { src = f2; dstOff = 4915200; CHW = 512 * 400;  e = (idx - 614400) * 8; }
                int b = e / CHW;
                int r = e - b * CHW;
                const float* s = src + (size_t)(b * 4 + 3) * CHW + r;
                float v[8];
                *(float4*)v       = *(const float4*)s;
                *(float4*)(v + 4) = *(const float4*)(s + 4);
                uint4 hi, lo; pack8(v, hi, lo);
                *(uint4*)(g_xh + dstOff + (size_t)b * CHW + r) = hi;
                *(uint4*)(g_xl + dstOff + (size_t)b * CHW + r) = lo;
            } else {              // weights
                int wi = idx - 716800;
                const float* w; size_t dstOff; int C, e;
                if (wi < 2048)       { w = w0; dstOff = 0;     C = 128; e = wi * 8; }
                else if (wi < 10240) { w = w1; dstOff = 16384; C = 256; e = (wi - 2048) * 8; }
                else                 { w = w2; dstOff = 81920; C = 512; e = (wi - 10240) * 8; }
                int o = e / C, k = e - o * C;
                const float* s = w + (size_t)o * (C + 4) + k;
                float v[8];
#pragma unroll
                for (int q = 0; q < 8; q++) v[q] = s[q];
                uint4 hi, lo; pack8(v, hi, lo);
                *(uint4*)(g_wh + dstOff + e) = hi;
                *(uint4*)(g_wl + dstOff + e) = lo;
            }
        }
        return;
    }

    // ---- reduce + transpose blocks: bid = bt*25 + ptile ----
    int bt  = bid / 25;
    int px0 = (bid - bt * 25) * 16;

    int sr = tid >> 4;
    int pc = tid & 15;

    const float* base = g_Lpart + (size_t)bt * NS_ * HW2 + px0 + pc;
    for (int s = sr; s < NS_; s += 16) {
        const float* src = base + (size_t)s * HW2;
        float a = 0.f;
#pragma unroll
        for (int cc = 0; cc < NCH; cc++)
            a += src[(size_t)cc * (12 * NS_ * HW2)];
        ts[s][pc] = a;
    }
    __syncthreads();

    int pxl = tid >> 4, sc = tid & 15;
    float* dst = g_Lt + ((size_t)bt * HW2 + px0 + pxl) * NS_;
    for (int s = sc; s < NS_; s += 16)
        dst[s] = ts[s][pxl];
}

// ---------------------------------------------------------------------------
// Kernel: warp-per-(b,t,px) softmax(81) + conv1(243->4) + BN + SiLU.
// grid = (100, B), 384 threads = 12 warps = 4 px x 3 t. Coalesced s-loads.
// ---------------------------------------------------------------------------
__global__ __launch_bounds__(384) void k_softmax1(
    const float* __restrict__ w1,
    const float* __restrict__ g1, const float* __restrict__ b1,
    const float* __restrict__ m1, const float* __restrict__ v1)
{
    __shared__ float w1s[992];
    __shared__ float opart[3][4][4];

    int b    = blockIdx.y;
    int tid  = threadIdx.x;
    int w    = tid >> 5;
    int lane = tid & 31;
    int pxl  = w / 3;
    int t    = w - pxl * 3;

    for (int i = tid; i < 992; i += 384) w1s[i] = (i < 972) ? w1[i] : 0.f;
    __syncthreads();

    int px = blockIdx.x * 4 + pxl;
    const float* Lb = g_Lt + ((size_t)(b * 3 + t) * HW2 + px) * NS_;

    bool has2 = lane < 17;
    float e0 = Lb[lane];
    float e1 = Lb[lane + 32];
    float e2 = has2 ? Lb[lane + 64] : -1e30f;

    float mx = fmaxf(fmaxf(e0, e1), e2);
#pragma unroll
    for (int off = 16; off; off >>= 1)
        mx = fmaxf(mx, __shfl_xor_sync(0xffffffffu, mx, off));

    float x0 = __expf(e0 - mx);
    float x1 = __expf(e1 - mx);
    float x2 = has2 ? __expf(e2 - mx) : 0.f;

    const float* wt = w1s + t * 81;
    float z  = x0 + x1 + x2;
    float u0 = wt[lane] * x0       + wt[lane + 32] * x1       + wt[lane + 64] * x2;
    float u1 = wt[243 + lane] * x0 + wt[243 + lane + 32] * x1 + wt[243 + lane + 64] * x2;
    float u2 = wt[486 + lane] * x0 + wt[486 + lane + 32] * x1 + wt[486 + lane + 64] * x2;
    float u3 = wt[729 + lane] * x0 + wt[729 + lane + 32] * x1 + wt[729 + lane + 64] * x2;

#pragma unroll
    for (int off = 16; off; off >>= 1) {
        z  += __shfl_xor_sync(0xffffffffu, z,  off);
        u0 += __shfl_xor_sync(0xffffffffu, u0, off);
        u1 += __shfl_xor_sync(0xffffffffu, u1, off);
        u2 += __shfl_xor_sync(0xffffffffu, u2, off);
        u3 += __shfl_xor_sync(0xffffffffu, u3, off);
    }

    if (lane == 0) {
        float rz = 1.f / z;
        opart[t][0][pxl] = u0 * rz;
        opart[t][1][pxl] = u1 * rz;
        opart[t][2][pxl] = u2 * rz;
        opart[t][3][pxl] = u3 * rz;
    }
    __syncthreads();

    if (tid < 16) {
        int pl = tid >> 2, oc = tid & 3;
        float o = opart[0][oc][pl] + opart[1][oc][pl] + opart[2][oc][pl];
        float sc = g1[oc] * rsqrtf(v1[oc] + 1e-3f);
        float yv = (o - m1[oc]) * sc + b1[oc];
        g_simf[((size_t)b * 4 + oc) * HW2 + blockIdx.x * 4 + pl]
            = yv / (1.f + __expf(-yv));
    }
}

// ---------------------------------------------------------------------------
// Kernel: unified tensor-core conv2. BM=64 x BN=128, 256 threads, occ 3.
// ALL staging via cp.async from pre-split bf16 planes (no in-loop math).
// pr tile computed in-prologue by bilinear from g_simf (identity at lvl2).
// smem: WH@0 WL@8K XH@16K XL@32K + prS@48K + wprS@50K = 51.2KB
// ---------------------------------------------------------------------------
struct LvP {
    const __nv_bfloat16 *xh, *xl, *wh, *wl;
    const float* w;
    const float* gg; const float* bb; const float* mm; const float* vv;
    float* out;
    int C, HW, Wo, nt, mt, blk0;
};
struct AllP { LvP lv[3]; };   // lv[0]=level2(heavy), lv[1]=level1, lv[2]=level0

__device__ __forceinline__ void ldsm4(uint32_t* r, uint32_t a) {
    asm volatile("ldmatrix.sync.aligned.m8n8.x4.shared.b16 {%0,%1,%2,%3},[%4];\n"
        : "=r"(r[0]), "=r"(r[1]), "=r"(r[2]), "=r"(r[3]) : "r"(a));
}
__device__ __forceinline__ void ldsm4t(uint32_t* r, uint32_t a) {
    asm volatile("ldmatrix.sync.aligned.m8n8.x4.trans.shared.b16 {%0,%1,%2,%3},[%4];\n"
        : "=r"(r[0]), "=r"(r[1]), "=r"(r[2]), "=r"(r[3]) : "r"(a));
}
__device__ __forceinline__ void mma16816(float* d, const uint32_t* a,
                                         uint32_t b0, uint32_t b1) {
    asm volatile("mma.sync.aligned.m16n8k16.row.col.f32.bf16.bf16.f32 "
        "{%0,%1,%2,%3},{%4,%5,%6,%7},{%8,%9},{%0,%1,%2,%3};\n"
        : "+f"(d[0]), "+f"(d[1]), "+f"(d[2]), "+f"(d[3])
        : "r"(a[0]), "r"(a[1]), "r"(a[2]), "r"(a[3]), "r"(b0), "r"(b1));
}

__global__ __launch_bounds__(256, 3) void k_conv2t(AllP P)
{
    extern __shared__ char smc[];
    const int OFF_WL = 8192, OFF_XH = 16384, OFF_XL = 32768;
    float* prS  = (float*)(smc + 49152);   // [4][128]
    float* wprS = (float*)(smc + 51200);   // [64][4]

    int bid = blockIdx.x;
    int li  = (bid >= P.lv[1].blk0) + (bid >= P.lv[2].blk0);
    LvP L = P.lv[li];

    int rb     = bid - L.blk0;
    int n_tile = rb % L.nt;
    int r2     = rb / L.nt;
    int m_tile = r2 % L.mt;
    int b      = r2 / L.mt;

    int ptile  = n_tile * 128;
    int K      = L.C + 4;
    int nchunk = L.C >> 6;

    int tid = threadIdx.x;
    int lane = tid & 31, wid = tid >> 5;
    int wm = wid >> 2, wn = wid & 3;

    uint32_t sb = (uint32_t)__cvta_generic_to_shared(smc);

    const __nv_bfloat16* xhb = L.xh + (size_t)b * L.C * L.HW;
    const __nv_bfloat16* xlb = L.xl + (size_t)b * L.C * L.HW;
    const __nv_bfloat16* whb = L.wh + (size_t)m_tile * 64 * L.C;
    const __nv_bfloat16* wlb = L.wl + (size_t)m_tile * 64 * L.C;

    // pr tile: bilinear from g_simf (identity when Wo == 20)
    for (int i = tid; i < 512; i += 256) {
        int j = i >> 7, n = i & 127;
        int px = ptile + n;
        float v = 0.f;
        if (px < L.HW) {
            const float* sp = g_simf + (size_t)(b * 4 + j) * HW2;
            if (L.Wo == 20) {
                v = sp[px];
            } else {
                int yo = px / L.Wo, xo = px - yo * L.Wo;
                float s19 = 19.f / (float)(L.Wo - 1);
                float cy = yo * s19, cx = xo * s19;
                int y0 = (int)cy, x0 = (int)cx;
                int y1 = min(y0 + 1, 19), x1 = min(x0 + 1, 19);
                float wy = cy - (float)y0, wx = cx - (float)x0;
                v = (1.f - wy) * ((1.f - wx) * sp[y0 * 20 + x0] + wx * sp[y0 * 20 + x1])
                  +         wy * ((1.f - wx) * sp[y1 * 20 + x0] + wx * sp[y1 * 20 + x1]);
            }
        }
        prS[i] = v;
    }
    {
        int o = tid >> 2, jj = tid & 3;
        wprS[tid] = L.w[(size_t)(m_tile * 64 + o) * K + L.C + jj];
    }

    float acc[2][4][4];
#pragma unroll
    for (int i = 0; i < 2; i++)
#pragma unroll
        for (int j = 0; j < 4; j++)
#pragma unroll
            for (int q = 0; q < 4; q++) acc[i][j][q] = 0.f;

    for (int c = 0; c < nchunk; c++) {
        int kbase = c * 64;
        // W planes (always in-bounds)
#pragma unroll
        for (int it = 0; it < 2; it++) {
            int item = tid + it * 256;
            int o = item >> 3, u = item & 7;
            size_t si = (size_t)o * L.C + kbase + u * 8;
            int off = o * 128 + ((u ^ (o & 7)) << 4);
            cpasync16(sb + off, whb + si);
            cpasync16(sb + OFF_WL + off, wlb + si);
        }
        // X planes (zero-fill when px tile exceeds HW)
#pragma unroll
        for (int it = 0; it < 4; it++) {
            int item = tid + it * 256;
            int kl = item >> 4, u = item & 15;
            int px0 = ptile + u * 8;
            size_t si = (size_t)(kbase + kl) * L.HW + px0;
            int off = kl * 256 + ((u ^ (kl & 7)) << 4);
            int sz = (px0 < L.HW) ? 16 : 0;
            cpasync16z(sb + OFF_XH + off, xhb + si, sz);
            cpasync16z(sb + OFF_XL + off, xlb + si, sz);
        }
        asm volatile("cp.async.commit_group;\n");
        asm volatile("cp.async.wait_group 0;\n" ::: "memory");
        __syncthreads();

#pragma unroll
        for (int ks = 0; ks < 4; ks++) {
            uint32_t ah[2][4], al[2][4];
#pragma unroll
            for (int mi = 0; mi < 2; mi++) {
                int rr = wm * 32 + mi * 16 + (lane & 15);
                int ku = ks * 2 + (lane >> 4);
                uint32_t a = sb + rr * 128 + ((ku ^ (rr & 7)) << 4);
                ldsm4(ah[mi], a);
                ldsm4(al[mi], a + OFF_WL);
            }
            uint32_t bh[2][4], bl[2][4];
#pragma unroll
            for (int g = 0; g < 2; g++) {
                int kr = ks * 16 + (lane & 15);
                int n0 = wn * 32 + g * 16 + ((lane >> 4) * 8);
                uint32_t a = sb + OFF_XH + kr * 256 + (((n0 >> 3) ^ (kr & 7)) << 4);
                ldsm4t(bh[g], a);
                ldsm4t(bl[g], a + (OFF_XL - OFF_XH));
            }
#pragma unroll
            for (int mi = 0; mi < 2; mi++)
#pragma unroll
                for (int g = 0; g < 2; g++)
#pragma unroll
                    for (int t = 0; t < 2; t++) {
                        int ni = g * 2 + t;
                        mma16816(acc[mi][ni], ah[mi], bh[g][2*t], bh[g][2*t + 1]);
                        mma16816(acc[mi][ni], ah[mi], bl[g][2*t], bl[g][2*t + 1]);
                        mma16816(acc[mi][ni], al[mi], bh[g][2*t], bh[g][2*t + 1]);
                    }
        }
        __syncthreads();
    }

    int ro = lane >> 2, co = (lane & 3) * 2;
#pragma unroll
    for (int mi = 0; mi < 2; mi++) {
#pragma unroll
        for (int half = 0; half < 2; half++) {
            int rloc = wm * 32 + mi * 16 + half * 8 + ro;
            int oo = m_tile * 64 + rloc;
            float w0 = wprS[rloc * 4 + 0], w1 = wprS[rloc * 4 + 1];
            float w2 = wprS[rloc * 4 + 2], w3 = wprS[rloc * 4 + 3];
            float sc = L.gg[oo] * rsqrtf(L.vv[oo] + 1e-3f);
            float sh = L.bb[oo] - L.mm[oo] * sc;
            float* ob = L.out + (size_t)(b * L.C + oo) * L.HW;
#pragma unroll
            for (int ni = 0; ni < 4; ni++) {
                int nloc = wn * 32 + ni * 8 + co;
                int px = ptile + nloc;
                if (px < L.HW) {
                    float p0 = acc[mi][ni][half * 2 + 0]
                             + w0 * prS[nloc]       + w1 * prS[128 + nloc]
                             + w2 * prS[256 + nloc] + w3 * prS[384 + nloc];
                    float p1 = acc[mi][ni][half * 2 + 1]
                             + w0 * prS[nloc + 1]       + w1 * prS[128 + nloc + 1]
                             + w2 * prS[256 + nloc + 1] + w3 * prS[384 + nloc + 1];
                    float y0 = p0 * sc + sh;
                    float y1 = p1 * sc + sh;
                    float2 r;
                    r.x = y0 / (1.f + __expf(-y0));
                    r.y = y1 / (1.f + __expf(-y1));
                    *(float2*)(ob + px) = r;
                }
            }
        }
    }
}

// ---------------------------------------------------------------------------
// Launch
// ---------------------------------------------------------------------------
extern "C" void kernel_launch(void* const* d_in, const int* in_sizes, int n_in,
                              void* d_out, int out_size)
{
    const float *f0 = nullptr, *f1 = nullptr, *f2 = nullptr, *w1 = nullptr;
    const float* bn1[4] = {nullptr, nullptr, nullptr, nullptr};
    const float* w2[3]  = {nullptr, nullptr, nullptr};
    const float* bn2[3][4];

    for (int i = 0; i < n_in; i++) {
        int sz = in_sizes[i];
        if (sz == 13107200)      f0 = (const float*)d_in[i];
        else if (sz == 6553600)  f1 = (const float*)d_in[i];
        else if (sz == 3276800)  f2 = (const float*)d_in[i];
        else if (sz == 972) {
            w1 = (const float*)d_in[i];
            for (int j = 0; j < 4; j++) bn1[j] = (const float*)d_in[i + 1 + j];
        } else if (sz == 16896) {
            w2[0] = (const float*)d_in[i];
            for (int j = 0; j < 4; j++) bn2[0][j] = (const float*)d_in[i + 1 + j];
        } else if (sz == 66560) {
            w2[1] = (const float*)d_in[i];
            for (int j = 0; j < 4; j++) bn2[1][j] = (const float*)d_in[i + 1 + j];
        } else if (sz == 264192) {
            w2[2] = (const float*)d_in[i];
            for (int j = 0; j < 4; j++) bn2[2][j] = (const float*)d_in[i + 1 + j];
        }
    }
    if (!f0 || !f1 || !f2 || !w1 || !w2[0] || !w2[1] || !w2[2]) return;

    int sim_smem = 16 * WROWS * CROW * 8;          // 66816 B
    cudaFuncSetAttribute(k_sim, cudaFuncAttributeMaxDynamicSharedMemorySize, sim_smem);
    cudaFuncSetAttribute(k_conv2t, cudaFuncAttributeMaxDynamicSharedMemorySize, 52224);

    void *xh, *xl, *wh, *wl;
    cudaGetSymbolAddress(&xh, g_xh);
    cudaGetSymbolAddress(&xl, g_xl);
    cudaGetSymbolAddress(&wh, g_wh);
    cudaGetSymbolAddress(&wl, g_wl);
    const __nv_bfloat16* XH = (const __nv_bfloat16*)xh;
    const __nv_bfloat16* XL = (const __nv_bfloat16*)xl;
    const __nv_bfloat16* WH = (const __nv_bfloat16*)wh;
    const __nv_bfloat16* WL = (const __nv_bfloat16*)wl;

    float* out0 = (float*)d_out;
    float* out1 = out0 + (size_t)B_ * 128 * 6400;
    float* out2 = out1 + (size_t)B_ * 256 * 1600;

    k_sim<<<dim3(NCH, B_, 2), 224, sim_smem>>>(f2);
    k_rcvt<<<1042, 256>>>(f0, f1, f2, w2[0], w2[1], w2[2]);
    k_softmax1<<<dim3(100, B_), 384>>>(w1, bn1[0], bn1[1], bn1[2], bn1[3]);

    // heavy-first block order: level2 (8 chunks) -> level1 (4) -> level0 (2)
    AllP P;
    P.lv[0] = { XH + 4915200, XL + 4915200, WH + 81920, WL + 81920, w2[2],
                bn2[2][0], bn2[2][1], bn2[2][2], bn2[2][3],
                out2, 512, 400, 20, 4, 8, 0 };      // 128 blocks
    P.lv[1] = { XH + 3276800, XL + 3276800, WH + 16384, WL + 16384, w2[1],
                bn2[1][0], bn2[1][1], bn2[1][2], bn2[1][3],
                out1, 256, 1600, 40, 13, 4, 128 };  // 208 blocks
    P.lv[2] = { XH, XL, WH, WL, w2[0],
                bn2[0][0], bn2[0][1], bn2[0][2], bn2[0][3],
                out0, 128, 6400, 80, 50, 2, 336 };  // 400 blocks
    int total_blocks = 128 + 208 + 400;   // 736

    k_conv2t<<<total_blocks, 256, 52224>>>(P);
}